// round 12
// baseline (speedup 1.0000x reference)
#include <cuda_runtime.h>
#include <cuda_fp16.h>
#include <cstdint>

// ---------------------------------------------------------------------------
// Fused gated-readout v7 (fp16 m16n8k16 via ldmatrix.x4, 2 CTAs/SM):
//   gate = sigmoid(MLP_g([h0;hT]))   512->128->256->128->256
//   val  = MLP_o(hT)                 256->128->256->128->256
//   out[b,:] = sum_n mask(b,n) * gate(b,n,:) * val(b,n,:)
// v7: no park buffer.  Value-L0 acc stays in registers through the gate path;
// gate sigmoid lives in 32 half2 registers with the mask folded in.  Freed
// smem funds a 5-slot weight ring (prefetch depth 4).  One sync per chunk.
// ---------------------------------------------------------------------------

#define THREADS     256
#define NCHUNK      36
#define CHUNK_BYTES 16384
#define BP          512                 // A-buffer row pitch (bytes), swizzled

#define BUF_OFF     0                   // 64 x 512 = 32768
#define SLOT_OFF    32768               // 5 x 16384 weight slots
#define MASK_OFF    114688              // 64 fp32
#define SMEM_BYTES  114944

__device__ __align__(16) unsigned short g_wpack[NCHUNK * 8192];

// A-operand k-unit offset of each chunk (16B units into the swizzled row)
__constant__ int c_u0[NCHUNK] = {0,8,16,24, 0,8,16,24, 0,8,16,24,
                                 0,4,8,12,  0,8,16,24, 0,4,8,12,
                                 0,4,8,12,  0,8,16,24, 0,4,8,12};

__device__ __forceinline__ void hmma(float* d,
                                     uint32_t a0, uint32_t a1, uint32_t a2, uint32_t a3,
                                     uint32_t b0, uint32_t b1) {
    asm volatile(
        "mma.sync.aligned.m16n8k16.row.col.f32.f16.f16.f32 "
        "{%0,%1,%2,%3}, {%4,%5,%6,%7}, {%8,%9}, {%0,%1,%2,%3};"
        : "+f"(d[0]), "+f"(d[1]), "+f"(d[2]), "+f"(d[3])
        : "r"(a0), "r"(a1), "r"(a2), "r"(a3), "r"(b0), "r"(b1));
}

#define LDSM4(r, a) asm volatile( \
    "ldmatrix.sync.aligned.m8n8.x4.shared.b16 {%0,%1,%2,%3}, [%4];" \
    : "=r"((r)[0]), "=r"((r)[1]), "=r"((r)[2]), "=r"((r)[3]) : "r"(a))

// ---------------------------------------------------------------------------
// pack: chunk image = groups of 8 n-rows: [group][k-unit][n&7][16B]
// ---------------------------------------------------------------------------
__global__ void pack_kernel(const float* __restrict__ gW0, const float* __restrict__ gW1,
                            const float* __restrict__ gW2, const float* __restrict__ gW3,
                            const float* __restrict__ oW0, const float* __restrict__ oW1,
                            const float* __restrict__ oW2, const float* __restrict__ oW3) {
    int c = blockIdx.x;
    const float* W; int Nl, ks;
    if (c < 8)       { W = gW0; Nl = 128; ks = c * 64; }
    else if (c < 12) { W = oW0; Nl = 128; ks = (c - 8) * 64; }
    else if (c < 16) { W = gW1; Nl = 256; ks = (c - 12) * 32; }
    else if (c < 20) { W = gW2; Nl = 128; ks = (c - 16) * 64; }
    else if (c < 24) { W = gW3; Nl = 256; ks = (c - 20) * 32; }
    else if (c < 28) { W = oW1; Nl = 256; ks = (c - 24) * 32; }
    else if (c < 32) { W = oW2; Nl = 128; ks = (c - 28) * 64; }
    else             { W = oW3; Nl = 256; ks = (c - 32) * 32; }
    const int GSH = (Nl == 128) ? 512 : 256;
    unsigned short* dst = g_wpack + (size_t)c * 8192;
    for (int i = threadIdx.x; i < 8192; i += blockDim.x) {
        int n, kl;
        if (Nl == 128) { n = i >> 6; kl = i & 63; }
        else           { n = i >> 5; kl = i & 31; }
        int di = (n >> 3) * GSH + (kl >> 3) * 64 + (n & 7) * 8 + (kl & 7);
        dst[di] = __half_as_ushort(__float2half_rn(W[(size_t)(ks + kl) * Nl + n]));
    }
}

// ---------------------------------------------------------------------------
__device__ __forceinline__ void prefetch(char* smdst, int idx, int tid) {
    const char* src = (const char*)g_wpack + (size_t)idx * CHUNK_BYTES;
    uint32_t sb = (uint32_t)__cvta_generic_to_shared(smdst);
    #pragma unroll
    for (int i = 0; i < 4; i++) {
        int o = (tid + i * 256) * 16;
        asm volatile("cp.async.cg.shared.global [%0], [%1], 16;" :: "r"(sb + o), "l"(src + o));
    }
    asm volatile("cp.async.commit_group;");
}

// acc[2mt x NT x 4] += A[warp 32-row slice] @ W[warp n-slice] over KB k16 blocks
template <int KB, int NT, int GS>
__device__ __forceinline__ void mma_chunk(uint32_t abase, int u0, uint32_t wbase,
                                          float* acc, int mb, int nb, int lane) {
    const int sx  = lane & 7;
    const int hi  = lane >> 4;
    const int kb2 = (lane >> 3) & 1;
    const int dn  = sx + ((lane & 16) >> 1);
    const uint32_t arow = abase + (uint32_t)((mb + (lane & 15)) * BP);
    const uint32_t bln  = wbase + (uint32_t)((dn >> 3) * GS + (dn & 7) * 16 + kb2 * 128
                                             + (nb >> 3) * GS);
    #pragma unroll
    for (int kb = 0; kb < KB; kb++) {
        const uint32_t aoff = (uint32_t)((((u0 + 2 * kb + hi) ^ sx)) << 4);
        uint32_t a0[4], a1[4];
        LDSM4(a0, arow + aoff);
        LDSM4(a1, arow + 16u * BP + aoff);
        #pragma unroll
        for (int j = 0; j < NT / 2; j++) {
            uint32_t b[4];
            LDSM4(b, bln + (uint32_t)(2 * j * GS + kb * 256));
            hmma(acc + (2 * j) * 4,          a0[0], a0[1], a0[2], a0[3], b[0], b[1]);
            hmma(acc + (2 * j + 1) * 4,      a0[0], a0[1], a0[2], a0[3], b[2], b[3]);
            hmma(acc + (NT + 2 * j) * 4,     a1[0], a1[1], a1[2], a1[3], b[0], b[1]);
            hmma(acc + (NT + 2 * j + 1) * 4, a1[0], a1[1], a1[2], a1[3], b[2], b[3]);
        }
    }
}

// relu(acc + bias) -> swizzled fp16 A operand rows in buf
template <int NT>
__device__ __forceinline__ void store_act(char* __restrict__ dst, const float* acc,
                                          const float* __restrict__ bias,
                                          int mb, int nb, int g, int t) {
    #pragma unroll
    for (int nt = 0; nt < NT; nt++) {
        int c = nb + nt * 8 + 2 * t;
        float b0 = __ldg(bias + c), b1 = __ldg(bias + c + 1);
        int u = c >> 3, wb = (c & 7) * 2;
        #pragma unroll
        for (int mt = 0; mt < 2; mt++) {
            int id = (mt * NT + nt) * 4;
            int r0 = mb + mt * 16 + g, r1 = r0 + 8;
            *(__half2*)(dst + r0 * BP + ((u ^ (r0 & 7)) << 4) + wb) =
                __floats2half2_rn(fmaxf(acc[id] + b0, 0.f), fmaxf(acc[id + 1] + b1, 0.f));
            *(__half2*)(dst + r1 * BP + ((u ^ (r1 & 7)) << 4) + wb) =
                __floats2half2_rn(fmaxf(acc[id + 2] + b0, 0.f), fmaxf(acc[id + 3] + b1, 0.f));
        }
    }
}

// fp32 global tile -> swizzled fp16 A buffer (+ optional mask)
__device__ __forceinline__ void stage_in(char* __restrict__ buf, const float* __restrict__ X,
                                         size_t row0, float* mask_sh, int tid, bool domask) {
    int r = tid >> 2, q = tid & 3, sx = r & 7;
    const float4* src = (const float4*)(X + (row0 + r) * 256);
    float s = 0.f;
    #pragma unroll
    for (int i = 0; i < 8; i++) {
        int u = q * 8 + i;
        float4 v0 = src[2 * u], v1 = src[2 * u + 1];
        if (domask) s += v0.x + v0.y + v0.z + v0.w + v1.x + v1.y + v1.z + v1.w;
        union { uint4 u4; __half2 h[4]; } pk;
        pk.h[0] = __floats2half2_rn(v0.x, v0.y);
        pk.h[1] = __floats2half2_rn(v0.z, v0.w);
        pk.h[2] = __floats2half2_rn(v1.x, v1.y);
        pk.h[3] = __floats2half2_rn(v1.z, v1.w);
        *(uint4*)(buf + r * BP + ((u ^ sx) << 4)) = pk.u4;
    }
    if (domask) {
        s += __shfl_xor_sync(0xffffffffu, s, 1);
        s += __shfl_xor_sync(0xffffffffu, s, 2);
        if (q == 0) mask_sh[r] = (s > 0.f) ? 1.f : 0.f;
    }
}

__device__ __forceinline__ void zero_n(float* a, int n) {
    #pragma unroll
    for (int i = 0; i < 64; i++) if (i < n) a[i] = 0.f;
}

__global__ void __launch_bounds__(THREADS, 2)
readout_kernel(const float* __restrict__ h0, const float* __restrict__ hT,
               const float* __restrict__ gb0, const float* __restrict__ gb1,
               const float* __restrict__ gb2, const float* __restrict__ gb3,
               const float* __restrict__ ob0, const float* __restrict__ ob1,
               const float* __restrict__ ob2, const float* __restrict__ ob3,
               float* __restrict__ out) {
    extern __shared__ __align__(16) char sm[];
    char*  buf     = sm + BUF_OFF;
    float* mask_sh = (float*)(sm + MASK_OFF);
    const uint32_t smb = (uint32_t)__cvta_generic_to_shared(sm);

    const int tid  = threadIdx.x;
    const int lane = tid & 31;
    const int w    = tid >> 5;
    const int wm   = w & 1, wn = w >> 1;          // 2 x 4 warp grid
    const int g    = lane >> 2, t = lane & 3;
    const int mb    = wm * 32;
    const int nb128 = wn * 32, nb256 = wn * 64;

    const size_t row0 = (size_t)blockIdx.x * 64;
    const int bidx = (int)(blockIdx.x >> 2);

    // prime prefetch pipeline: 4 chunks in flight
    #pragma unroll
    for (int i = 0; i < 4; i++)
        prefetch(sm + SLOT_OFF + i * CHUNK_BYTES, i, tid);
    stage_in(buf, h0, row0, mask_sh, tid, true);

    float accA[32], accV[32], accB[64];
    uint32_t gsig[32];                            // masked sigmoid gate (half2 pairs)
    zero_n(accA, 32); zero_n(accV, 32);

    for (int idx = 0; idx < NCHUNK; idx++) {
        if      (idx < 33)  asm volatile("cp.async.wait_group 3;");
        else if (idx == 33) asm volatile("cp.async.wait_group 2;");
        else if (idx == 34) asm volatile("cp.async.wait_group 1;");
        else                asm volatile("cp.async.wait_group 0;");
        __syncthreads();
        // slot (idx+4)%5 == (idx-1)%5 was freed by the previous iteration
        if (idx + 4 < NCHUNK)
            prefetch(sm + SLOT_OFF + ((idx + 4) % 5) * CHUNK_BYTES, idx + 4, tid);

        const uint32_t ws = smb + SLOT_OFF + (uint32_t)((idx % 5) * CHUNK_BYTES);
        const int u0 = c_u0[idx];

        if (idx < 8)       mma_chunk<4,4,1024>(smb, u0, ws, accA, mb, nb128, lane);  // gate L0
        else if (idx < 12) mma_chunk<4,4,1024>(smb, u0, ws, accV, mb, nb128, lane);  // value L0
        else if (idx < 16) mma_chunk<2,8,512> (smb, u0, ws, accB, mb, nb256, lane);  // gate L1
        else if (idx < 20) mma_chunk<4,4,1024>(smb, u0, ws, accA, mb, nb128, lane);  // gate L2
        else if (idx < 24) mma_chunk<2,8,512> (smb, u0, ws, accB, mb, nb256, lane);  // gate L3
        else if (idx < 28) mma_chunk<2,8,512> (smb, u0, ws, accB, mb, nb256, lane);  // value L1
        else if (idx < 32) mma_chunk<4,4,1024>(smb, u0, ws, accA, mb, nb128, lane);  // value L2
        else               mma_chunk<2,8,512> (smb, u0, ws, accB, mb, nb256, lane);  // value L3

        if (idx == 3) {                                   // h0 -> hT restage
            __syncthreads();
            stage_in(buf, hT, row0, nullptr, tid, false);
        } else if (idx == 11) {                           // gate L0 act -> buf (accV stays in regs)
            __syncthreads();
            store_act<4>(buf, accA, gb0, mb, nb128, g, t);
            zero_n(accB, 64);
        } else if (idx == 15) {
            __syncthreads();
            store_act<8>(buf, accB, gb1, mb, nb256, g, t);
            zero_n(accA, 32);
        } else if (idx == 19) {
            __syncthreads();
            store_act<4>(buf, accA, gb2, mb, nb128, g, t);
            zero_n(accB, 64);
        } else if (idx == 23) {
            __syncthreads();
            // gsig = mask * sigmoid(gateL3 + gb3), in half2 registers
            #pragma unroll
            for (int nt = 0; nt < 8; nt++) {
                int c = nb256 + nt * 8 + 2 * t;
                float b0 = __ldg(gb3 + c), b1 = __ldg(gb3 + c + 1);
                #pragma unroll
                for (int mt = 0; mt < 2; mt++) {
                    int id = (mt * 8 + nt) * 4;
                    int r0 = mb + mt * 16 + g, r1 = r0 + 8;
                    float m0 = mask_sh[r0], m1 = mask_sh[r1];
                    float s0 = m0 / (1.f + __expf(-(accB[id]     + b0)));
                    float s1 = m0 / (1.f + __expf(-(accB[id + 1] + b1)));
                    float s2 = m1 / (1.f + __expf(-(accB[id + 2] + b0)));
                    float s3 = m1 / (1.f + __expf(-(accB[id + 3] + b1)));
                    __half2 p0 = __floats2half2_rn(s0, s1);
                    __half2 p1 = __floats2half2_rn(s2, s3);
                    gsig[(mt * 8 + nt) * 2]     = *(uint32_t*)&p0;
                    gsig[(mt * 8 + nt) * 2 + 1] = *(uint32_t*)&p1;
                }
            }
            // value L0 act (held in accV registers since idx 11) -> buf
            store_act<4>(buf, accV, ob0, mb, nb128, g, t);
            zero_n(accB, 64);
        } else if (idx == 27) {
            __syncthreads();
            store_act<8>(buf, accB, ob1, mb, nb256, g, t);
            zero_n(accA, 32);
        } else if (idx == 31) {
            __syncthreads();
            store_act<4>(buf, accA, ob2, mb, nb128, g, t);
            zero_n(accB, 64);
        } else if (idx == 35) {                           // combine + node reduction
            #pragma unroll
            for (int nt = 0; nt < 8; nt++) {
                int c = nb256 + nt * 8 + 2 * t;
                float b0 = __ldg(ob3 + c), b1 = __ldg(ob3 + c + 1);
                float s0 = 0.f, s1 = 0.f;
                #pragma unroll
                for (int mt = 0; mt < 2; mt++) {
                    int id = (mt * 8 + nt) * 4;
                    __half2 hg0 = *(__half2*)&gsig[(mt * 8 + nt) * 2];
                    __half2 hg1 = *(__half2*)&gsig[(mt * 8 + nt) * 2 + 1];
                    s0 += __low2float(hg0)  * (accB[id]     + b0)
                        + __low2float(hg1)  * (accB[id + 2] + b0);
                    s1 += __high2float(hg0) * (accB[id + 1] + b1)
                        + __high2float(hg1) * (accB[id + 3] + b1);
                }
                s0 += __shfl_xor_sync(0xffffffffu, s0, 4);
                s1 += __shfl_xor_sync(0xffffffffu, s1, 4);
                s0 += __shfl_xor_sync(0xffffffffu, s0, 8);
                s1 += __shfl_xor_sync(0xffffffffu, s1, 8);
                s0 += __shfl_xor_sync(0xffffffffu, s0, 16);
                s1 += __shfl_xor_sync(0xffffffffu, s1, 16);
                if (lane < 4) {
                    atomicAdd(&out[bidx * 256 + c],     s0);
                    atomicAdd(&out[bidx * 256 + c + 1], s1);
                }
            }
        }
    }
}

extern "C" void kernel_launch(void* const* d_in, const int* in_sizes, int n_in,
                              void* d_out, int out_size) {
    const float* h0  = (const float*)d_in[0];
    const float* hT  = (const float*)d_in[1];
    const float* gW0 = (const float*)d_in[2];  const float* gb0 = (const float*)d_in[3];
    const float* gW1 = (const float*)d_in[4];  const float* gb1 = (const float*)d_in[5];
    const float* gW2 = (const float*)d_in[6];  const float* gb2 = (const float*)d_in[7];
    const float* gW3 = (const float*)d_in[8];  const float* gb3 = (const float*)d_in[9];
    const float* oW0 = (const float*)d_in[10]; const float* ob0 = (const float*)d_in[11];
    const float* oW1 = (const float*)d_in[12]; const float* ob1 = (const float*)d_in[13];
    const float* oW2 = (const float*)d_in[14]; const float* ob2 = (const float*)d_in[15];
    const float* oW3 = (const float*)d_in[16]; const float* ob3 = (const float*)d_in[17];
    float* out = (float*)d_out;

    cudaFuncSetAttribute(readout_kernel,
                         cudaFuncAttributeMaxDynamicSharedMemorySize, SMEM_BYTES);
    cudaMemsetAsync(d_out, 0, (size_t)out_size * sizeof(float), 0);
    pack_kernel<<<NCHUNK, 256>>>(gW0, gW1, gW2, gW3, oW0, oW1, oW2, oW3);
    readout_kernel<<<2048, THREADS, SMEM_BYTES>>>(
        h0, hT, gb0, gb1, gb2, gb3, ob0, ob1, ob2, ob3, out);
}

// round 13
// speedup vs baseline: 1.0276x; 1.0276x over previous
#include <cuda_runtime.h>
#include <cuda_fp16.h>
#include <cstdint>

// ---------------------------------------------------------------------------
// Fused gated-readout v8 (fp16 m16n8k16 via ldmatrix.x4, 2 CTAs/SM):
//   gate = sigmoid(MLP_g([h0;hT]))   512->128->256->128->256
//   val  = MLP_o(hT)                 256->128->256->128->256
//   out[b,:] = sum_n mask(b,n) * gate(b,n,:) * val(b,n,:)
// v8: three rotating act buffers (A256 / A128 / PARK) so every layer writes a
// buffer disjoint from the one it reads -> NO pre-store syncs (loop-top sync
// orders).  Value L1 reads the park directly (no copy).  Gate sigmoid in 32
// half2 regs with mask folded (accV parks early -> no v7 register collision).
// ---------------------------------------------------------------------------

#define THREADS     256
#define NCHUNK      36
#define CHUNK_BYTES 16384

#define A256_OFF    0                   // 64 x 512  (256-col acts, pitch 512)
#define A128_OFF    32768               // 64 x 256  (128-col acts, pitch 256)
#define PARK_OFF    49152               // 64 x 256  (value-L0 act, pitch 256)
#define SLOT_OFF    65536               // 3 x 16384 weight slots
#define MASK_OFF    114688              // 64 fp32
#define SMEM_BYTES  114944

__device__ __align__(16) unsigned short g_wpack[NCHUNK * 8192];

// A-operand k-unit offset of each chunk (16B units into the swizzled row)
__constant__ int c_u0[NCHUNK] = {0,8,16,24, 0,8,16,24, 0,8,16,24,
                                 0,4,8,12,  0,8,16,24, 0,4,8,12,
                                 0,4,8,12,  0,8,16,24, 0,4,8,12};

__device__ __forceinline__ void hmma(float* d,
                                     uint32_t a0, uint32_t a1, uint32_t a2, uint32_t a3,
                                     uint32_t b0, uint32_t b1) {
    asm volatile(
        "mma.sync.aligned.m16n8k16.row.col.f32.f16.f16.f32 "
        "{%0,%1,%2,%3}, {%4,%5,%6,%7}, {%8,%9}, {%0,%1,%2,%3};"
        : "+f"(d[0]), "+f"(d[1]), "+f"(d[2]), "+f"(d[3])
        : "r"(a0), "r"(a1), "r"(a2), "r"(a3), "r"(b0), "r"(b1));
}

#define LDSM4(r, a) asm volatile( \
    "ldmatrix.sync.aligned.m8n8.x4.shared.b16 {%0,%1,%2,%3}, [%4];" \
    : "=r"((r)[0]), "=r"((r)[1]), "=r"((r)[2]), "=r"((r)[3]) : "r"(a))

// ---------------------------------------------------------------------------
// pack: chunk image = groups of 8 n-rows: [group][k-unit][n&7][16B]
// ---------------------------------------------------------------------------
__global__ void pack_kernel(const float* __restrict__ gW0, const float* __restrict__ gW1,
                            const float* __restrict__ gW2, const float* __restrict__ gW3,
                            const float* __restrict__ oW0, const float* __restrict__ oW1,
                            const float* __restrict__ oW2, const float* __restrict__ oW3) {
    int c = blockIdx.x;
    const float* W; int Nl, ks;
    if (c < 8)       { W = gW0; Nl = 128; ks = c * 64; }
    else if (c < 12) { W = oW0; Nl = 128; ks = (c - 8) * 64; }
    else if (c < 16) { W = gW1; Nl = 256; ks = (c - 12) * 32; }
    else if (c < 20) { W = gW2; Nl = 128; ks = (c - 16) * 64; }
    else if (c < 24) { W = gW3; Nl = 256; ks = (c - 20) * 32; }
    else if (c < 28) { W = oW1; Nl = 256; ks = (c - 24) * 32; }
    else if (c < 32) { W = oW2; Nl = 128; ks = (c - 28) * 64; }
    else             { W = oW3; Nl = 256; ks = (c - 32) * 32; }
    const int GSH = (Nl == 128) ? 512 : 256;
    unsigned short* dst = g_wpack + (size_t)c * 8192;
    for (int i = threadIdx.x; i < 8192; i += blockDim.x) {
        int n, kl;
        if (Nl == 128) { n = i >> 6; kl = i & 63; }
        else           { n = i >> 5; kl = i & 31; }
        int di = (n >> 3) * GSH + (kl >> 3) * 64 + (n & 7) * 8 + (kl & 7);
        dst[di] = __half_as_ushort(__float2half_rn(W[(size_t)(ks + kl) * Nl + n]));
    }
}

// ---------------------------------------------------------------------------
__device__ __forceinline__ void prefetch(char* smdst, int idx, int tid) {
    const char* src = (const char*)g_wpack + (size_t)idx * CHUNK_BYTES;
    uint32_t sb = (uint32_t)__cvta_generic_to_shared(smdst);
    #pragma unroll
    for (int i = 0; i < 4; i++) {
        int o = (tid + i * 256) * 16;
        asm volatile("cp.async.cg.shared.global [%0], [%1], 16;" :: "r"(sb + o), "l"(src + o));
    }
    asm volatile("cp.async.commit_group;");
}

// acc[2mt x NT x 4] += A[warp 32-row slice] @ W[warp n-slice] over KB k16 blocks
// PB = A-buffer row pitch in bytes (512 for 256-col acts, 256 for 128-col)
template <int KB, int NT, int GS, int PB>
__device__ __forceinline__ void mma_chunk(uint32_t abase, int u0, uint32_t wbase,
                                          float* acc, int mb, int nb, int lane) {
    const int sx  = lane & 7;
    const int hi  = lane >> 4;
    const int kb2 = (lane >> 3) & 1;
    const int dn  = sx + ((lane & 16) >> 1);
    const uint32_t arow = abase + (uint32_t)((mb + (lane & 15)) * PB);
    const uint32_t bln  = wbase + (uint32_t)((dn >> 3) * GS + (dn & 7) * 16 + kb2 * 128
                                             + (nb >> 3) * GS);
    #pragma unroll
    for (int kb = 0; kb < KB; kb++) {
        const uint32_t aoff = (uint32_t)((((u0 + 2 * kb + hi) ^ sx)) << 4);
        uint32_t a0[4], a1[4];
        LDSM4(a0, arow + aoff);
        LDSM4(a1, arow + 16u * PB + aoff);
        #pragma unroll
        for (int j = 0; j < NT / 2; j++) {
            uint32_t b[4];
            LDSM4(b, bln + (uint32_t)(2 * j * GS + kb * 256));
            hmma(acc + (2 * j) * 4,          a0[0], a0[1], a0[2], a0[3], b[0], b[1]);
            hmma(acc + (2 * j + 1) * 4,      a0[0], a0[1], a0[2], a0[3], b[2], b[3]);
            hmma(acc + (NT + 2 * j) * 4,     a1[0], a1[1], a1[2], a1[3], b[0], b[1]);
            hmma(acc + (NT + 2 * j + 1) * 4, a1[0], a1[1], a1[2], a1[3], b[2], b[3]);
        }
    }
}

// relu(acc + bias) -> swizzled fp16 A operand rows (pitch PB)
template <int NT, int PB>
__device__ __forceinline__ void store_act(char* __restrict__ dst, const float* acc,
                                          const float* __restrict__ bias,
                                          int mb, int nb, int g, int t) {
    #pragma unroll
    for (int nt = 0; nt < NT; nt++) {
        int c = nb + nt * 8 + 2 * t;
        float b0 = __ldg(bias + c), b1 = __ldg(bias + c + 1);
        int u = c >> 3, wb = (c & 7) * 2;
        #pragma unroll
        for (int mt = 0; mt < 2; mt++) {
            int id = (mt * NT + nt) * 4;
            int r0 = mb + mt * 16 + g, r1 = r0 + 8;
            *(__half2*)(dst + r0 * PB + ((u ^ (r0 & 7)) << 4) + wb) =
                __floats2half2_rn(fmaxf(acc[id] + b0, 0.f), fmaxf(acc[id + 1] + b1, 0.f));
            *(__half2*)(dst + r1 * PB + ((u ^ (r1 & 7)) << 4) + wb) =
                __floats2half2_rn(fmaxf(acc[id + 2] + b0, 0.f), fmaxf(acc[id + 3] + b1, 0.f));
        }
    }
}

// fp32 global tile -> swizzled fp16 A256 buffer (+ optional mask)
__device__ __forceinline__ void stage_in(char* __restrict__ buf, const float* __restrict__ X,
                                         size_t row0, float* mask_sh, int tid, bool domask) {
    int r = tid >> 2, q = tid & 3, sx = r & 7;
    const float4* src = (const float4*)(X + (row0 + r) * 256);
    float s = 0.f;
    #pragma unroll
    for (int i = 0; i < 8; i++) {
        int u = q * 8 + i;
        float4 v0 = src[2 * u], v1 = src[2 * u + 1];
        if (domask) s += v0.x + v0.y + v0.z + v0.w + v1.x + v1.y + v1.z + v1.w;
        union { uint4 u4; __half2 h[4]; } pk;
        pk.h[0] = __floats2half2_rn(v0.x, v0.y);
        pk.h[1] = __floats2half2_rn(v0.z, v0.w);
        pk.h[2] = __floats2half2_rn(v1.x, v1.y);
        pk.h[3] = __floats2half2_rn(v1.z, v1.w);
        *(uint4*)(buf + r * 512 + ((u ^ sx) << 4)) = pk.u4;
    }
    if (domask) {
        s += __shfl_xor_sync(0xffffffffu, s, 1);
        s += __shfl_xor_sync(0xffffffffu, s, 2);
        if (q == 0) mask_sh[r] = (s > 0.f) ? 1.f : 0.f;
    }
}

__device__ __forceinline__ void zero_n(float* a, int n) {
    #pragma unroll
    for (int i = 0; i < 64; i++) if (i < n) a[i] = 0.f;
}

__global__ void __launch_bounds__(THREADS, 2)
readout_kernel(const float* __restrict__ h0, const float* __restrict__ hT,
               const float* __restrict__ gb0, const float* __restrict__ gb1,
               const float* __restrict__ gb2, const float* __restrict__ gb3,
               const float* __restrict__ ob0, const float* __restrict__ ob1,
               const float* __restrict__ ob2, const float* __restrict__ ob3,
               float* __restrict__ out) {
    extern __shared__ __align__(16) char sm[];
    char*  bufA256 = sm + A256_OFF;
    char*  bufA128 = sm + A128_OFF;
    char*  bufPARK = sm + PARK_OFF;
    float* mask_sh = (float*)(sm + MASK_OFF);
    const uint32_t smb = (uint32_t)__cvta_generic_to_shared(sm);
    const uint32_t aA256 = smb + A256_OFF;
    const uint32_t aA128 = smb + A128_OFF;
    const uint32_t aPARK = smb + PARK_OFF;

    const int tid  = threadIdx.x;
    const int lane = tid & 31;
    const int w    = tid >> 5;
    const int wm   = w & 1, wn = w >> 1;          // 2 x 4 warp grid
    const int g    = lane >> 2, t = lane & 3;
    const int mb    = wm * 32;
    const int nb128 = wn * 32, nb256 = wn * 64;

    const size_t row0 = (size_t)blockIdx.x * 64;
    const int bidx = (int)(blockIdx.x >> 2);

    prefetch(sm + SLOT_OFF, 0, tid);
    prefetch(sm + SLOT_OFF + CHUNK_BYTES, 1, tid);
    stage_in(bufA256, h0, row0, mask_sh, tid, true);

    float accA[32], accV[32], accB[64];
    uint32_t gsig[32];                            // masked sigmoid gate (half2 pairs)
    zero_n(accA, 32); zero_n(accV, 32);

    for (int idx = 0; idx < NCHUNK; idx++) {
        if (idx == NCHUNK - 1) asm volatile("cp.async.wait_group 0;");
        else                   asm volatile("cp.async.wait_group 1;");
        __syncthreads();
        // slot (idx+2)%3 == slot consumed at idx-1, freed by the barrier above
        if (idx + 2 < NCHUNK)
            prefetch(sm + SLOT_OFF + ((idx + 2) % 3) * CHUNK_BYTES, idx + 2, tid);

        const uint32_t ws = smb + SLOT_OFF + (uint32_t)((idx % 3) * CHUNK_BYTES);
        const int u0 = c_u0[idx];

        if (idx < 8)       mma_chunk<4,4,1024,512>(aA256, u0, ws, accA, mb, nb128, lane); // gate L0
        else if (idx < 12) mma_chunk<4,4,1024,512>(aA256, u0, ws, accV, mb, nb128, lane); // value L0
        else if (idx < 16) mma_chunk<2,8,512,256> (aA128, u0, ws, accB, mb, nb256, lane); // gate L1
        else if (idx < 20) mma_chunk<4,4,1024,512>(aA256, u0, ws, accA, mb, nb128, lane); // gate L2
        else if (idx < 24) mma_chunk<2,8,512,256> (aA128, u0, ws, accB, mb, nb256, lane); // gate L3
        else if (idx < 28) mma_chunk<2,8,512,256> (aPARK, u0, ws, accB, mb, nb256, lane); // value L1
        else if (idx < 32) mma_chunk<4,4,1024,512>(aA256, u0, ws, accA, mb, nb128, lane); // value L2
        else               mma_chunk<2,8,512,256> (aA128, u0, ws, accB, mb, nb256, lane); // value L3

        // Epilogues: every store targets a buffer DISJOINT from the one the
        // current layer reads -> no pre-store sync (next loop-top sync orders).
        if (idx == 3) {                                   // h0 -> hT restage (same buffer: sync)
            __syncthreads();
            stage_in(bufA256, hT, row0, nullptr, tid, false);
        } else if (idx == 7) {                            // gate L0 out -> A128
            store_act<4,256>(bufA128, accA, gb0, mb, nb128, g, t);
            zero_n(accA, 32);
        } else if (idx == 11) {                           // value L0 out -> PARK
            store_act<4,256>(bufPARK, accV, ob0, mb, nb128, g, t);
            zero_n(accB, 64);
        } else if (idx == 15) {                           // gate L1 out -> A256
            store_act<8,512>(bufA256, accB, gb1, mb, nb256, g, t);
            zero_n(accB, 64);
        } else if (idx == 19) {                           // gate L2 out -> A128
            store_act<4,256>(bufA128, accA, gb2, mb, nb128, g, t);
            zero_n(accA, 32);
        } else if (idx == 23) {                           // gate L3 -> masked sigmoid in regs
            #pragma unroll
            for (int nt = 0; nt < 8; nt++) {
                int c = nb256 + nt * 8 + 2 * t;
                float b0 = __ldg(gb3 + c), b1 = __ldg(gb3 + c + 1);
                #pragma unroll
                for (int mt = 0; mt < 2; mt++) {
                    int id = (mt * 8 + nt) * 4;
                    int r0 = mb + mt * 16 + g, r1 = r0 + 8;
                    float m0 = mask_sh[r0], m1 = mask_sh[r1];
                    float s0 = m0 / (1.f + __expf(-(accB[id]     + b0)));
                    float s1 = m0 / (1.f + __expf(-(accB[id + 1] + b1)));
                    float s2 = m1 / (1.f + __expf(-(accB[id + 2] + b0)));
                    float s3 = m1 / (1.f + __expf(-(accB[id + 3] + b1)));
                    __half2 p0 = __floats2half2_rn(s0, s1);
                    __half2 p1 = __floats2half2_rn(s2, s3);
                    gsig[(mt * 8 + nt) * 2]     = *(uint32_t*)&p0;
                    gsig[(mt * 8 + nt) * 2 + 1] = *(uint32_t*)&p1;
                }
            }
            zero_n(accB, 64);
        } else if (idx == 27) {                           // value L1 out -> A256
            store_act<8,512>(bufA256, accB, ob1, mb, nb256, g, t);
            zero_n(accB, 64);
        } else if (idx == 31) {                           // value L2 out -> A128
            store_act<4,256>(bufA128, accA, ob2, mb, nb128, g, t);
        } else if (idx == 35) {                           // combine + node reduction
            #pragma unroll
            for (int nt = 0; nt < 8; nt++) {
                int c = nb256 + nt * 8 + 2 * t;
                float b0 = __ldg(ob3 + c), b1 = __ldg(ob3 + c + 1);
                float s0 = 0.f, s1 = 0.f;
                #pragma unroll
                for (int mt = 0; mt < 2; mt++) {
                    int id = (mt * 8 + nt) * 4;
                    __half2 hg0 = *(__half2*)&gsig[(mt * 8 + nt) * 2];
                    __half2 hg1 = *(__half2*)&gsig[(mt * 8 + nt) * 2 + 1];
                    s0 += __low2float(hg0)  * (accB[id]     + b0)
                        + __low2float(hg1)  * (accB[id + 2] + b0);
                    s1 += __high2float(hg0) * (accB[id + 1] + b1)
                        + __high2float(hg1) * (accB[id + 3] + b1);
                }
                s0 += __shfl_xor_sync(0xffffffffu, s0, 4);
                s1 += __shfl_xor_sync(0xffffffffu, s1, 4);
                s0 += __shfl_xor_sync(0xffffffffu, s0, 8);
                s1 += __shfl_xor_sync(0xffffffffu, s1, 8);
                s0 += __shfl_xor_sync(0xffffffffu, s0, 16);
                s1 += __shfl_xor_sync(0xffffffffu, s1, 16);
                if (lane < 4) {
                    atomicAdd(&out[bidx * 256 + c],     s0);
                    atomicAdd(&out[bidx * 256 + c + 1], s1);
                }
            }
        }
    }
}

extern "C" void kernel_launch(void* const* d_in, const int* in_sizes, int n_in,
                              void* d_out, int out_size) {
    const float* h0  = (const float*)d_in[0];
    const float* hT  = (const float*)d_in[1];
    const float* gW0 = (const float*)d_in[2];  const float* gb0 = (const float*)d_in[3];
    const float* gW1 = (const float*)d_in[4];  const float* gb1 = (const float*)d_in[5];
    const float* gW2 = (const float*)d_in[6];  const float* gb2 = (const float*)d_in[7];
    const float* gW3 = (const float*)d_in[8];  const float* gb3 = (const float*)d_in[9];
    const float* oW0 = (const float*)d_in[10]; const float* ob0 = (const float*)d_in[11];
    const float* oW1 = (const float*)d_in[12]; const float* ob1 = (const float*)d_in[13];
    const float* oW2 = (const float*)d_in[14]; const float* ob2 = (const float*)d_in[15];
    const float* oW3 = (const float*)d_in[16]; const float* ob3 = (const float*)d_in[17];
    float* out = (float*)d_out;

    cudaFuncSetAttribute(readout_kernel,
                         cudaFuncAttributeMaxDynamicSharedMemorySize, SMEM_BYTES);
    cudaMemsetAsync(d_out, 0, (size_t)out_size * sizeof(float), 0);
    pack_kernel<<<NCHUNK, 256>>>(gW0, gW1, gW2, gW3, oW0, oW1, oW2, oW3);
    readout_kernel<<<2048, THREADS, SMEM_BYTES>>>(
        h0, hT, gb0, gb1, gb2, gb3, ob0, ob1, ob2, ob3, out);
}